// round 5
// baseline (speedup 1.0000x reference)
#include <cuda_runtime.h>
#include <cuda_fp16.h>

// Problem constants (fixed by the reference)
#define Nn   10000      // nodes
#define Ee   80000      // edges (excl. self loops)
#define Gg   16         // B*DAYS graphs
#define HC   128        // H*C_OUT
#define NEG  0.2f
#define GC   4          // graphs per warp in k_gat
#define PR   8          // rows per block in k_proj
#define NPROJ (Nn / PR)             // 1250 proj blocks
#define NHIST ((Ee + 127) / 128)    // 625 hist blocks

// ---- device scratch (allocation-free rule: __device__ globals) ----
__device__ __align__(16) __half g_emb_h[Nn * HC];     // fp16 projected embedding [N,128]
__device__ __align__(16) float g_asrc[Nn * 4];        // per-row src logits [N,H]
__device__ __align__(16) float g_adst[Nn * 4];        // per-row dst logits [N,H]
__device__ __align__(16) int g_xT[Nn * Gg];           // transposed x: [N,16]
__device__ __align__(16) int g_edge_u[Ee * Gg];       // resolved per-edge node idx [E,16]
__device__ int g_row_ptr[Nn + 1];
__device__ int g_cursor[Nn];                          // INVARIANT: all-zero at kernel_launch entry
                                                      // (zero at load; k_gat re-zeroes each launch)

// ---------------- fused projection + histogram ----------------
// blocks [0, NPROJ): project 8 embedding rows; compute logits; build xT
// blocks [NPROJ, NPROJ+NHIST): histogram edge dst counts into g_cursor
__global__ void __launch_bounds__(128) k_projhist(const float* __restrict__ emb,
                                                  const float* __restrict__ W,
                                                  const float* __restrict__ att_s,
                                                  const float* __restrict__ att_d,
                                                  const int* __restrict__ x,
                                                  const int* __restrict__ adj) {
    int c = threadIdx.x;  // 0..127

    if (blockIdx.x >= NPROJ) {
        int e = (blockIdx.x - NPROJ) * 128 + c;
        if (e < Ee) atomicAdd(&g_cursor[adj[Ee + e]], 1);  // adj[1] = dst
        return;
    }

    int n0 = blockIdx.x * PR;

    // W column for this channel, once per block
    float wcol[32];
#pragma unroll
    for (int k = 0; k < 32; k++) wcol[k] = W[k * 128 + c];

    // 8 embedding rows, coalesced (256 floats / 128 threads)
    __shared__ float se[PR][32];
    __shared__ float sws[32 * 8];   // fused W@att: [k][(srcdst<<2)|h]
#pragma unroll
    for (int i = 0; i < 2; i++) {
        int idx = i * 128 + c;
        se[idx >> 5][idx & 31] = emb[n0 * 32 + idx];
    }

    // redundant per-block ws: ws[k][j] = sum_c W[k,h*32+c]*att[h,c]
#pragma unroll
    for (int t = c; t < 256; t += 128) {
        int k = t >> 3, j = t & 7, h = j & 3;
        const float* av = (j < 4) ? att_s : att_d;
        float a = 0.f;
#pragma unroll
        for (int c2 = 0; c2 < 32; c2++)
            a = fmaf(W[k * 128 + h * 32 + c2], av[h * 32 + c2], a);
        sws[t] = a;
    }

    // x transpose (8 consecutive n per graph g)
    {
        int g = c >> 3, i = c & 7;
        g_xT[(n0 + i) * Gg + g] = x[g * Nn + n0 + i];
    }
    __syncthreads();

    // projected embedding, fp16
#pragma unroll
    for (int r = 0; r < PR; r++) {
        float acc = 0.f;
#pragma unroll
        for (int k = 0; k < 32; k++) acc = fmaf(se[r][k], wcol[k], acc);
        g_emb_h[(n0 + r) * 128 + c] = __float2half(acc);
    }

    // logits: 64 dots (8 rows x 8 cols)
    if (c < 64) {
        int r = c >> 3, j = c & 7, h = j & 3;
        float acc = 0.f;
#pragma unroll
        for (int k = 0; k < 32; k++) acc = fmaf(se[r][k], sws[k * 8 + j], acc);
        if (j < 4) g_asrc[(n0 + r) * 4 + h] = acc;
        else       g_adst[(n0 + r) * 4 + h] = acc;
    }
}

// ---------------- single-block exclusive scan: g_cursor -> g_row_ptr (+copy) ----------------
__global__ void k_scan() {
    const int CH = 10;  // 1024*10 >= 10000
    __shared__ int part[1024];
    int t = threadIdx.x;
    int base = t * CH;
    int loc[CH];
    int sum = 0;
#pragma unroll
    for (int i = 0; i < CH; i++) {
        int idx = base + i;
        int v = (idx < Nn) ? g_cursor[idx] : 0;
        loc[i] = sum;
        sum += v;
    }
    part[t] = sum;
    __syncthreads();
    for (int off = 1; off < 1024; off <<= 1) {
        int v = (t >= off) ? part[t - off] : 0;
        __syncthreads();
        part[t] += v;
        __syncthreads();
    }
    int prev = (t > 0) ? part[t - 1] : 0;
#pragma unroll
    for (int i = 0; i < CH; i++) {
        int idx = base + i;
        if (idx < Nn) {
            int p = prev + loc[i];
            g_row_ptr[idx] = p;
            g_cursor[idx] = p;
        }
    }
    if (t == 0) g_row_ptr[Nn] = part[1023];
}

// ---------------- CSR fill + edge index resolve ----------------
// For each edge: place into CSR slot p, and materialize all 16 graphs' source
// node ids (xT[src]) at g_edge_u[p] so k_gat has a 1-level gather chain.
__global__ void k_fillres(const int* __restrict__ adj) {
    int e = blockIdx.x * blockDim.x + threadIdx.x;
    if (e < Ee) {
        int d = adj[Ee + e];
        int j = adj[e];
        int p = atomicAdd(&g_cursor[d], 1);
        const int4* src = (const int4*)(g_xT + j * Gg);
        int4 a0 = src[0], a1 = src[1], a2 = src[2], a3 = src[3];
        int4* dst = (int4*)(g_edge_u + p * Gg);
        dst[0] = a0; dst[1] = a1; dst[2] = a2; dst[3] = a3;
    }
}

// ---------------- main GAT kernel: one warp per (4-graph chunk, dst node) ----------------
__device__ __forceinline__ float4 load_msg(int u, int lane) {
    uint4 q = *(const uint4*)(g_emb_h + u * 128 + 4 * lane);  // one LDG.128
    __half2 h0 = *(__half2*)&q.x, h1 = *(__half2*)&q.y;
    float2 a = __half22float2(h0), b = __half22float2(h1);
    return make_float4(a.x, a.y, b.x, b.y);
}

__global__ void __launch_bounds__(256) k_gat(const float* __restrict__ bias,
                                             float* __restrict__ out) {
    int gid = blockIdx.x * blockDim.x + threadIdx.x;
    if (gid < Nn) g_cursor[gid] = 0;   // restore invariant for next launch/replay

    int w = gid >> 5;
    int lane = threadIdx.x & 31;
    const int NW = Nn * (Gg / GC);
    if (w >= NW) return;
    int v = w >> 2;          // adjacent warps share v -> L1 hits on structure
    int gc = w & 3;          // graph chunk: graphs gc*4 .. gc*4+3
    int h = lane >> 3;

    int4 vx = *(const int4*)(g_xT + v * Gg + gc * GC);
    int vemb[GC] = {vx.x, vx.y, vx.z, vx.w};

    float adst[GC], s[GC];
    float4 acc[GC];
#pragma unroll
    for (int i = 0; i < GC; i++) {
        adst[i] = g_adst[vemb[i] * 4 + h];
        float a0 = g_asrc[vemb[i] * 4 + h] + adst[i];
        a0 = fmaxf(a0, NEG * a0);
        float e0 = __expf(a0);
        s[i] = e0;
        float4 m = load_msg(vemb[i], lane);
        acc[i] = make_float4(e0 * m.x, e0 * m.y, e0 * m.z, e0 * m.w);
    }

    int idx = g_row_ptr[v];
    int end = g_row_ptr[v + 1];
    int4 ux = make_int4(0, 0, 0, 0);
    if (idx < end) ux = *(const int4*)(g_edge_u + idx * Gg + gc * GC);
    while (idx < end) {
        int nidx = idx + 1;
        int4 uxn = ux;
        if (nidx < end) uxn = *(const int4*)(g_edge_u + nidx * Gg + gc * GC);
        int u[GC] = {ux.x, ux.y, ux.z, ux.w};
        float a[GC];
        float4 m[GC];
#pragma unroll
        for (int i = 0; i < GC; i++) {
            a[i] = g_asrc[u[i] * 4 + h] + adst[i];
            m[i] = load_msg(u[i], lane);
        }
#pragma unroll
        for (int i = 0; i < GC; i++) {
            float ai = fmaxf(a[i], NEG * a[i]);
            float wi = __expf(ai);
            s[i] += wi;
            acc[i].x = fmaf(wi, m[i].x, acc[i].x);
            acc[i].y = fmaf(wi, m[i].y, acc[i].y);
            acc[i].z = fmaf(wi, m[i].z, acc[i].z);
            acc[i].w = fmaf(wi, m[i].w, acc[i].w);
        }
        ux = uxn;
        idx = nidx;
    }

    float4 b = *(const float4*)(bias + 4 * lane);
#pragma unroll
    for (int i = 0; i < GC; i++) {
        float inv = 1.f / (s[i] + 1e-16f);
        float4 o;
        o.x = fmaf(acc[i].x, inv, b.x);
        o.y = fmaf(acc[i].y, inv, b.y);
        o.z = fmaf(acc[i].z, inv, b.z);
        o.w = fmaf(acc[i].w, inv, b.w);
        int g = gc * GC + i;
        *(float4*)(out + ((size_t)g * Nn + v) * 128 + 4 * lane) = o;
    }
}

extern "C" void kernel_launch(void* const* d_in, const int* in_sizes, int n_in,
                              void* d_out, int out_size) {
    const int*   x     = (const int*)d_in[0];     // [B,DAYS,N] = [16,10000]
    const int*   adj   = (const int*)d_in[1];     // [2,E]
    const float* emb   = (const float*)d_in[2];   // [N,32]
    const float* W     = (const float*)d_in[3];   // [32,128]
    const float* att_s = (const float*)d_in[4];   // [4,32]
    const float* att_d = (const float*)d_in[5];   // [4,32]
    const float* bias  = (const float*)d_in[6];   // [128]
    float* out = (float*)d_out;                   // [16,10000,128]

    k_projhist<<<NPROJ + NHIST, 128>>>(emb, W, att_s, att_d, x, adj);
    k_scan<<<1, 1024>>>();
    k_fillres<<<(Ee + 255) / 256, 256>>>(adj);

    int total_warps = Nn * (Gg / GC);
    k_gat<<<(total_warps * 32 + 255) / 256, 256>>>(bias, out);
}